// round 16
// baseline (speedup 1.0000x reference)
#include <cuda_runtime.h>
#include <cuda_fp16.h>
#include <math.h>
#include <stdint.h>

#define NNODES 50000
#define NEDGES 800000
#define ETOT   (NEDGES + NNODES)
#define NLBL   100000
#define FIN    128
#define HH     4
#define CC     64
#define DD     256

// ---------------- scratch (device globals; no allocation allowed) ----------
__device__ int    g_flag64_e;
__device__ int    g_rowptr[NNODES + 1];
__device__ int    g_fill[NNODES];
__device__ int    g_incl[NNODES];
__device__ int    g_bsum[256];
__device__ int    g_csr_src[ETOT];
__device__ int    g_esrc[ETOT];
__device__ int    g_edst[ETOT];
__device__ int    g_lu[NLBL];
__device__ int    g_lv[NLBL];
__device__ __half g_xh[(size_t)NNODES * FIN];   // x in fp16
__device__ __half g_hbuf[(size_t)NNODES * DD];  // GEMM output (fp16) / agg input
__device__ __half g_zh[(size_t)NNODES * DD];    // agg output (fp16) / GEMM input
__device__ float  g_als[NNODES * HH];
__device__ float  g_ald[NNODES * HH];
__device__ float  g_pr[(size_t)NNODES * 128];   // scorer P|R per node (fp32)
__device__ __half g_Wt1h[256 * 128];            // W1^T  fp16
__device__ __half g_Wt2h[256 * 256];            // W2^T  fp16
__device__ __half g_Wtsh[128 * 256];            // [Ws1_top|Ws1_bot]^T fp16

// ============================ helpers =======================================
__device__ __forceinline__ uint32_t pack_h2(float a, float b) {
    __half2 h = __floats2half2_rn(a, b);
    return *(uint32_t*)&h;
}

__device__ __forceinline__ void mma16816(float& c0, float& c1, float& c2, float& c3,
                                         uint32_t a0, uint32_t a1, uint32_t a2, uint32_t a3,
                                         uint32_t b0, uint32_t b1) {
    asm volatile(
        "mma.sync.aligned.m16n8k16.row.col.f32.f16.f16.f32 "
        "{%0,%1,%2,%3}, {%4,%5,%6,%7}, {%8,%9}, {%0,%1,%2,%3};"
        : "+f"(c0), "+f"(c1), "+f"(c2), "+f"(c3)
        : "r"(a0), "r"(a1), "r"(a2), "r"(a3), "r"(b0), "r"(b1));
}

__device__ __forceinline__ void ldsm_x4(uint32_t& r0, uint32_t& r1,
                                        uint32_t& r2, uint32_t& r3, uint32_t addr) {
    asm volatile("ldmatrix.sync.aligned.m8n8.x4.shared.b16 {%0,%1,%2,%3}, [%4];"
                 : "=r"(r0), "=r"(r1), "=r"(r2), "=r"(r3) : "r"(addr));
}

__device__ __forceinline__ void ldsm_x2(uint32_t& r0, uint32_t& r1, uint32_t addr) {
    asm volatile("ldmatrix.sync.aligned.m8n8.x2.shared.b16 {%0,%1}, [%2];"
                 : "=r"(r0), "=r"(r1) : "r"(addr));
}

__device__ __forceinline__ int check_is_i64(const long long* q) {
    int ok = 1;
#pragma unroll
    for (int i = 0; i < 8; i++) {
        long long v = q[i];
        if (v < 0 || v >= NNODES) ok = 0;
    }
    return ok;
}

// ---------------- init: zero hist + label conversion + dtype flag -----------
__global__ void init_k(const void* ei, const void* eli) {
    int i = blockIdx.x * blockDim.x + threadIdx.x;
    if (i < NNODES) g_fill[i] = 0;
    if (i < NLBL) {
        if (check_is_i64((const long long*)eli)) {
            const long long* q = (const long long*)eli;
            g_lu[i] = (int)q[i]; g_lv[i] = (int)q[NLBL + i];
        } else {
            const int* q = (const int*)eli;
            g_lu[i] = q[i]; g_lv[i] = q[NLBL + i];
        }
    }
    if (i == 0) g_flag64_e = check_is_i64((const long long*)ei);
}

// ---------------- edge conversion + self loops + histogram ------------------
__global__ void build_edges(const void* ei) {
    int i = blockIdx.x * blockDim.x + threadIdx.x;
    if (i >= ETOT) return;
    int s, d;
    if (i < NEDGES) {
        if (g_flag64_e) {
            const long long* q = (const long long*)ei;
            s = (int)q[i]; d = (int)q[NEDGES + i];
        } else {
            const int* q = (const int*)ei;
            s = q[i]; d = q[NEDGES + i];
        }
    } else {
        s = i - NEDGES; d = s;   // self loop
    }
    g_esrc[i] = s; g_edst[i] = d;
    atomicAdd(&g_fill[d], 1);
}

// ---------------- CSR build: hierarchical scan -------------------------------
__global__ void scan1_k() {
    __shared__ int sh[256];
    int t = threadIdx.x;
    int i = blockIdx.x * 256 + t;
    int v = (i < NNODES) ? g_fill[i] : 0;
    sh[t] = v; __syncthreads();
    for (int o = 1; o < 256; o <<= 1) {
        int a = (t >= o) ? sh[t - o] : 0;
        __syncthreads();
        sh[t] += a;
        __syncthreads();
    }
    if (i < NNODES) g_incl[i] = sh[t];
    if (t == 255) g_bsum[blockIdx.x] = sh[255];
}

__global__ void scan2_k(int nb) {
    __shared__ int sh[256];
    int t = threadIdx.x;
    int v = (t < nb) ? g_bsum[t] : 0;
    sh[t] = v; __syncthreads();
    for (int o = 1; o < 256; o <<= 1) {
        int a = (t >= o) ? sh[t - o] : 0;
        __syncthreads();
        sh[t] += a;
        __syncthreads();
    }
    if (t < nb) g_bsum[t] = sh[t] - v;   // exclusive
}

__global__ void scan3_k() {
    int i = blockIdx.x * blockDim.x + threadIdx.x;
    if (i >= NNODES) return;
    int tot = g_bsum[i >> 8] + g_incl[i];
    int orig = g_fill[i];
    g_rowptr[i + 1] = tot;
    g_fill[i] = tot - orig;              // exclusive offsets for scatter
    if (i == 0) g_rowptr[0] = 0;
}

__global__ void scatter_k() {
    int i = blockIdx.x * blockDim.x + threadIdx.x;
    if (i >= ETOT) return;
    int pos = atomicAdd(&g_fill[g_edst[i]], 1);
    g_csr_src[pos] = g_esrc[i];
}

// ---------------- weight prep: coalesced 32x32 tiled transposes -> fp16 -----
__device__ __forceinline__ void tile_transpose(const float* __restrict__ src,
                                               __half* __restrict__ dst,
                                               int R, int C, int tileIdx,
                                               float (*sh)[33]) {
    int tilesC = C >> 5;
    int tc = tileIdx % tilesC, tr = tileIdx / tilesC;
    int lx = threadIdx.x & 31, ly = threadIdx.x >> 5;   // ly: 0..7
#pragma unroll
    for (int j = 0; j < 32; j += 8)
        sh[ly + j][lx] = src[(size_t)(tr * 32 + ly + j) * C + tc * 32 + lx];
    __syncthreads();
#pragma unroll
    for (int j = 0; j < 32; j += 8)
        dst[(size_t)(tc * 32 + ly + j) * R + tr * 32 + lx] =
            __float2half_rn(sh[lx][ly + j]);
}

__global__ void prep_weights_k(const float* __restrict__ W1,
                               const float* __restrict__ W2,
                               const float* __restrict__ Ws1) {
    __shared__ float sh[32][33];
    int b = blockIdx.x;
    if (b < 32) {
        tile_transpose(W1, g_Wt1h, 128, 256, b, sh);         // -> [256][128]
    } else if (b < 96) {
        tile_transpose(W2, g_Wt2h, 256, 256, b - 32, sh);    // -> [256][256]
    } else if (b < 112) {
        tile_transpose(Ws1, g_Wtsh, 256, 64, b - 96, sh);    // top -> rows [0,64)
    } else {
        tile_transpose(Ws1 + 256 * 64, g_Wtsh + 64 * 256, 256, 64, b - 112, sh);
    }
}

// ---------------- convert x -> fp16 (8 floats per thread) -------------------
__global__ void conv_x_k(const float* __restrict__ x) {
    int i = blockIdx.x * blockDim.x + threadIdx.x;
    if (i >= NNODES * FIN / 8) return;
    const float4* xp = (const float4*)x;
    float4 a = xp[i * 2], b = xp[i * 2 + 1];
    uint4 u = { pack_h2(a.x, a.y), pack_h2(a.z, a.w),
                pack_h2(b.x, b.y), pack_h2(b.z, b.w) };
    ((uint4*)g_xh)[i] = u;
}

// ---------------- fp16 mma.sync GEMM, double-buffered smem ------------------
// C[M,NTR] = A[M,KDIM] @ Bt[NTR,KDIM]^T   (half gmem, fp32 accum)
// Block tile 128x64, 8 warps (4 in M x 2 in N), warp tile 32x32.
// Ping-pong buffers: ONE __syncthreads per K-chunk (compute buf b, store
// prefetched regs to buf b^1, sync). Thread maps / ldmatrix identical to
// the measured-good single-buffer version.
// LOGITS: fused head logits (64-col block == one head). OUTH: write half2 C.
template <int KDIM, int NTR, bool LOGITS, bool OUTH>
__global__ void __launch_bounds__(256) gemm_mma(
    const __half* __restrict__ A, const __half* __restrict__ Bt,
    void* __restrict__ Cv, int M,
    const float* __restrict__ a_src, const float* __restrict__ a_dst,
    float* __restrict__ als, float* __restrict__ ald)
{
    // smem in half2 units; pitch 20 (80B rows); two buffers each
    __shared__ uint32_t As[2 * 128 * 20];
    __shared__ uint32_t Bs[2 * 64 * 20];
    __shared__ float red[4][128];
    constexpr int ABUF = 128 * 20;   // words
    constexpr int BBUF = 64 * 20;

    int tid = threadIdx.x;
    int wid = tid >> 5, lane = tid & 31;
    int warp_m = wid & 3, warp_n = wid >> 2;
    int g = lane >> 2, t = lane & 3;

    int rowBase = blockIdx.y * 128;
    int colBase = blockIdx.x * 64;

    uint32_t shA = (uint32_t)__cvta_generic_to_shared(As);
    uint32_t shB = (uint32_t)__cvta_generic_to_shared(Bs);
    uint32_t aAddr = shA + (uint32_t)((warp_m * 32 + (lane & 15)) * 80 + ((lane >> 4) & 1) * 16);
    uint32_t bAddr = shB + (uint32_t)((warp_n * 32 + (lane & 7)) * 80 + ((lane >> 3) & 1) * 16);

    float c[2][4][4];
#pragma unroll
    for (int i = 0; i < 2; i++)
#pragma unroll
        for (int j = 0; j < 4; j++)
#pragma unroll
            for (int k = 0; k < 4; k++) c[i][j][k] = 0.f;

    constexpr int NC = KDIM / 32;
    const uint2 zero2 = {0u, 0u};
    uint2 ra[4], rb[2];

    // prefetch chunk 0, stage into buffer 0
    {
#pragma unroll
        for (int j = 0; j < 4; j++) {
            int idx = tid + 256 * j;
            int r = idx >> 3, q = idx & 7;
            int gr = rowBase + r;
            ra[j] = (gr < M) ? *(const uint2*)(A + (size_t)gr * KDIM + q * 4) : zero2;
        }
#pragma unroll
        for (int j = 0; j < 2; j++) {
            int idx = tid + 256 * j;
            int r = idx >> 3, q = idx & 7;
            rb[j] = *(const uint2*)(Bt + (size_t)(colBase + r) * KDIM + q * 4);
        }
#pragma unroll
        for (int j = 0; j < 4; j++) {
            int idx = tid + 256 * j;
            int r = idx >> 3, q = idx & 7;
            *(uint2*)&As[r * 20 + q * 2] = ra[j];
        }
#pragma unroll
        for (int j = 0; j < 2; j++) {
            int idx = tid + 256 * j;
            int r = idx >> 3, q = idx & 7;
            *(uint2*)&Bs[r * 20 + q * 2] = rb[j];
        }
    }
    __syncthreads();

    for (int kc = 0; kc < NC; kc++) {
        // issue next chunk's global loads
        if (kc + 1 < NC) {
            int k0 = (kc + 1) * 32;
#pragma unroll
            for (int j = 0; j < 4; j++) {
                int idx = tid + 256 * j;
                int r = idx >> 3, q = idx & 7;
                int gr = rowBase + r;
                ra[j] = (gr < M) ? *(const uint2*)(A + (size_t)gr * KDIM + k0 + q * 4)
                                 : zero2;
            }
#pragma unroll
            for (int j = 0; j < 2; j++) {
                int idx = tid + 256 * j;
                int r = idx >> 3, q = idx & 7;
                rb[j] = *(const uint2*)(Bt + (size_t)(colBase + r) * KDIM + k0 + q * 4);
            }
        }

        // compute from buffer kc&1
        uint32_t aBufOff = (uint32_t)((kc & 1) * ABUF * 4);
        uint32_t bBufOff = (uint32_t)((kc & 1) * BBUF * 4);
#pragma unroll
        for (int ks = 0; ks < 2; ks++) {
            uint32_t koff = ks * 32;   // bytes
            uint32_t a[2][4];
#pragma unroll
            for (int tm = 0; tm < 2; tm++)
                ldsm_x4(a[tm][0], a[tm][1], a[tm][2], a[tm][3],
                        aAddr + aBufOff + tm * 16 * 80 + koff);
            uint32_t b[4][2];
#pragma unroll
            for (int tn = 0; tn < 4; tn++)
                ldsm_x2(b[tn][0], b[tn][1], bAddr + bBufOff + tn * 8 * 80 + koff);
#pragma unroll
            for (int tm = 0; tm < 2; tm++)
#pragma unroll
                for (int tn = 0; tn < 4; tn++)
                    mma16816(c[tm][tn][0], c[tm][tn][1], c[tm][tn][2], c[tm][tn][3],
                             a[tm][0], a[tm][1], a[tm][2], a[tm][3],
                             b[tn][0], b[tn][1]);
        }

        // store next chunk into the other buffer; one sync per chunk
        if (kc + 1 < NC) {
            int bsel = (kc + 1) & 1;
#pragma unroll
            for (int j = 0; j < 4; j++) {
                int idx = tid + 256 * j;
                int r = idx >> 3, q = idx & 7;
                *(uint2*)&As[bsel * ABUF + r * 20 + q * 2] = ra[j];
            }
#pragma unroll
            for (int j = 0; j < 2; j++) {
                int idx = tid + 256 * j;
                int r = idx >> 3, q = idx & 7;
                *(uint2*)&Bs[bsel * BBUF + r * 20 + q * 2] = rb[j];
            }
            __syncthreads();
        }
    }

    // epilogue: store C (+ fused logits)
    float ps[2][2], pd[2][2];
    if (LOGITS) {
#pragma unroll
        for (int tm = 0; tm < 2; tm++)
            ps[tm][0] = ps[tm][1] = pd[tm][0] = pd[tm][1] = 0.f;
    }
#pragma unroll
    for (int tm = 0; tm < 2; tm++) {
        int r0 = rowBase + warp_m * 32 + tm * 16 + g;
        int r1 = r0 + 8;
#pragma unroll
        for (int tn = 0; tn < 4; tn++) {
            int col = colBase + warp_n * 32 + tn * 8 + t * 2;
            if (LOGITS) {
                float s0 = a_src[col], s1 = a_src[col + 1];
                float d0 = a_dst[col], d1 = a_dst[col + 1];
                ps[tm][0] += c[tm][tn][0] * s0 + c[tm][tn][1] * s1;
                pd[tm][0] += c[tm][tn][0] * d0 + c[tm][tn][1] * d1;
                ps[tm][1] += c[tm][tn][2] * s0 + c[tm][tn][3] * s1;
                pd[tm][1] += c[tm][tn][2] * d0 + c[tm][tn][3] * d1;
            }
            if (OUTH) {
                __half* C = (__half*)Cv;
                if (r0 < M)
                    *(__half2*)(C + (size_t)r0 * NTR + col) =
                        __floats2half2_rn(c[tm][tn][0], c[tm][tn][1]);
                if (r1 < M)
                    *(__half2*)(C + (size_t)r1 * NTR + col) =
                        __floats2half2_rn(c[tm][tn][2], c[tm][tn][3]);
            } else {
                float* C = (float*)Cv;
                if (r0 < M)
                    *(float2*)(C + (size_t)r0 * NTR + col) = make_float2(c[tm][tn][0], c[tm][tn][1]);
                if (r1 < M)
                    *(float2*)(C + (size_t)r1 * NTR + col) = make_float2(c[tm][tn][2], c[tm][tn][3]);
            }
        }
    }
    if (LOGITS) {
#pragma unroll
        for (int tm = 0; tm < 2; tm++)
#pragma unroll
            for (int rr = 0; rr < 2; rr++) {
#pragma unroll
                for (int o = 1; o < 4; o <<= 1) {
                    ps[tm][rr] += __shfl_xor_sync(0xffffffffu, ps[tm][rr], o);
                    pd[tm][rr] += __shfl_xor_sync(0xffffffffu, pd[tm][rr], o);
                }
            }
        __syncthreads();
        if (t == 0) {
#pragma unroll
            for (int tm = 0; tm < 2; tm++) {
                int rl = warp_m * 32 + tm * 16 + g;
                red[warp_n * 2 + 0][rl]     = ps[tm][0];
                red[warp_n * 2 + 0][rl + 8] = ps[tm][1];
                red[warp_n * 2 + 1][rl]     = pd[tm][0];
                red[warp_n * 2 + 1][rl + 8] = pd[tm][1];
            }
        }
        __syncthreads();
        if (tid < 128) {
            int row = rowBase + tid;
            if (row < M) {
                int h = blockIdx.x;   // 64-col block == one head
                als[row * 4 + h] = red[0][tid] + red[2][tid];
                ald[row * 4 + h] = red[1][tid] + red[3][tid];
            }
        }
    }
}

// ---------------- fused softmax + aggregation + bias + ELU (fp16 out) -------
__global__ void __launch_bounds__(256) aggregate_k(const float* __restrict__ bias) {
    int warp = threadIdx.x >> 5, lane = threadIdx.x & 31;
    int n = blockIdx.x * 8 + warp;
    if (n >= NNODES) return;
    int hh = lane >> 3;                         // 8 channels per lane -> head
    int beg = g_rowptr[n], end = g_rowptr[n + 1];
    const __half* hb = g_hbuf;
    float aldn = g_ald[n * 4 + hh];

    float acc[8] = {};
    float psum = 0.f;
#pragma unroll 2
    for (int k = beg; k < end; k++) {
        int s = g_csr_src[k];
        float e = g_als[s * 4 + hh] + aldn;
        float v = e > 0.f ? e : 0.2f * e;
        float w = __expf(v);
        psum += w;
        uint4 u = *(const uint4*)(hb + (size_t)s * 256 + lane * 8);
        const __half2* ph = (const __half2*)&u;
#pragma unroll
        for (int j = 0; j < 4; j++) {
            float2 f = __half22float2(ph[j]);
            acc[2 * j]     = fmaf(w, f.x, acc[2 * j]);
            acc[2 * j + 1] = fmaf(w, f.y, acc[2 * j + 1]);
        }
    }
    float inv = 1.f / psum;
    float4 b0 = *(const float4*)&bias[lane * 8];
    float4 b1 = *(const float4*)&bias[lane * 8 + 4];
    float o[8];
    o[0] = fmaf(acc[0], inv, b0.x); o[1] = fmaf(acc[1], inv, b0.y);
    o[2] = fmaf(acc[2], inv, b0.z); o[3] = fmaf(acc[3], inv, b0.w);
    o[4] = fmaf(acc[4], inv, b1.x); o[5] = fmaf(acc[5], inv, b1.y);
    o[6] = fmaf(acc[6], inv, b1.z); o[7] = fmaf(acc[7], inv, b1.w);
#pragma unroll
    for (int j = 0; j < 8; j++)
        o[j] = o[j] > 0.f ? o[j] : (__expf(o[j]) - 1.f);
    uint4 uo = { pack_h2(o[0], o[1]), pack_h2(o[2], o[3]),
                 pack_h2(o[4], o[5]), pack_h2(o[6], o[7]) };
    *(uint4*)(g_zh + (size_t)n * 256 + lane * 8) = uo;
}

// ---------------- fused scorer: out = relu(P[u]+R[v]+bs1) . Ws2 + bs2 -------
__global__ void score_k(const float* __restrict__ bs1, const float* __restrict__ Ws2,
                        const float* __restrict__ bs2, float* __restrict__ out) {
    int e = (blockIdx.x * blockDim.x + threadIdx.x) >> 5;
    int lane = threadIdx.x & 31;
    if (e >= NLBL) return;
    int u = g_lu[e], v = g_lv[e];
    const float* pu = g_pr + (size_t)u * 128;
    const float* rv = g_pr + (size_t)v * 128 + 64;
    float s = 0.f;
#pragma unroll
    for (int j = 0; j < 2; j++) {
        int c = lane + j * 32;
        float h = pu[c] + rv[c] + bs1[c];
        h = fmaxf(h, 0.f);
        s = fmaf(h, Ws2[c], s);
    }
#pragma unroll
    for (int o = 16; o; o >>= 1) s += __shfl_xor_sync(0xffffffffu, s, o);
    if (!lane) out[e] = s + bs2[0];
}

// ---------------- launcher --------------------------------------------------
extern "C" void kernel_launch(void* const* d_in, const int* in_sizes, int n_in,
                              void* d_out, int out_size) {
    const float* x   = (const float*)d_in[0];
    const void*  ei  = d_in[1];
    const void*  eli = d_in[2];
    const float* W1  = (const float*)d_in[3];
    const float* as1 = (const float*)d_in[4];
    const float* ad1 = (const float*)d_in[5];
    const float* b1  = (const float*)d_in[6];
    const float* W2  = (const float*)d_in[7];
    const float* as2 = (const float*)d_in[8];
    const float* ad2 = (const float*)d_in[9];
    const float* b2  = (const float*)d_in[10];
    const float* Ws1 = (const float*)d_in[11];
    const float* bs1 = (const float*)d_in[12];
    const float* Ws2 = (const float*)d_in[13];
    const float* bs2 = (const float*)d_in[14];
    float* out = (float*)d_out;

    __half *xh, *hptr, *zh, *wt1h, *wt2h, *wtsh;
    float *prptr, *alsp, *aldp;
    cudaGetSymbolAddress((void**)&xh, g_xh);
    cudaGetSymbolAddress((void**)&hptr, g_hbuf);
    cudaGetSymbolAddress((void**)&zh, g_zh);
    cudaGetSymbolAddress((void**)&wt1h, g_Wt1h);
    cudaGetSymbolAddress((void**)&wt2h, g_Wt2h);
    cudaGetSymbolAddress((void**)&wtsh, g_Wtsh);
    cudaGetSymbolAddress((void**)&prptr, g_pr);
    cudaGetSymbolAddress((void**)&alsp, g_als);
    cudaGetSymbolAddress((void**)&aldp, g_ald);

    // side stream + fork/join events (created once, on the non-capture
    // correctness call; host-side only, no device memory involved)
    static cudaStream_t s2 = nullptr;
    static cudaEvent_t evFork = nullptr, evJoin = nullptr;
    if (!s2) {
        cudaStreamCreateWithFlags(&s2, cudaStreamNonBlocking);
        cudaEventCreateWithFlags(&evFork, cudaEventDisableTiming);
        cudaEventCreateWithFlags(&evJoin, cudaEventDisableTiming);
    }

    const int nb = (NNODES + 255) / 256;      // 196
    const int mrows = (NNODES + 127) / 128;   // 391

    // fork: CSR build chain on s2, concurrent with weight/x prep + GEMM1
    cudaEventRecord(evFork, 0);
    cudaStreamWaitEvent(s2, evFork, 0);

    init_k<<<(NLBL + 255) / 256, 256, 0, s2>>>(ei, eli);
    build_edges<<<(ETOT + 255) / 256, 256, 0, s2>>>(ei);
    scan1_k<<<nb, 256, 0, s2>>>();
    scan2_k<<<1, 256, 0, s2>>>(nb);
    scan3_k<<<(NNODES + 255) / 256, 256, 0, s2>>>();
    scatter_k<<<(ETOT + 255) / 256, 256, 0, s2>>>();
    cudaEventRecord(evJoin, s2);

    // main stream: weight + x prep, then layer-1 GEMM (independent of CSR)
    prep_weights_k<<<128, 256>>>(W1, W2, Ws1);
    conv_x_k<<<(NNODES * FIN / 8 + 255) / 256, 256>>>(x);
    gemm_mma<128, 256, true, true><<<dim3(4, mrows), 256>>>(
        xh, wt1h, hptr, NNODES, as1, ad1, alsp, aldp);

    // join: aggregation needs both CSR and logits
    cudaStreamWaitEvent(0, evJoin, 0);

    // ---- layer 1 edge pipeline (softmax fused into aggregation) ----
    aggregate_k<<<(NNODES + 7) / 8, 256>>>(b1);

    // ---- layer 2 ----
    gemm_mma<256, 256, true, true><<<dim3(4, mrows), 256>>>(zh, wt2h, hptr, NNODES,
                                                            as2, ad2, alsp, aldp);
    aggregate_k<<<(NNODES + 7) / 8, 256>>>(b2);

    // ---- scorer ----
    gemm_mma<256, 128, false, false><<<dim3(2, mrows), 256>>>(zh, wtsh, prptr, NNODES,
                                                              nullptr, nullptr, nullptr, nullptr);
    score_k<<<(NLBL + 7) / 8, 256>>>(bs1, Ws2, bs2, out);
}

// round 17
// speedup vs baseline: 1.0080x; 1.0080x over previous
#include <cuda_runtime.h>
#include <cuda_fp16.h>
#include <math.h>
#include <stdint.h>

#define NNODES 50000
#define NEDGES 800000
#define ETOT   (NEDGES + NNODES)
#define NLBL   100000
#define FIN    128
#define HH     4
#define CC     64
#define DD     256

// ---------------- scratch (device globals; no allocation allowed) ----------
__device__ int    g_flag64_e;
__device__ int    g_rowptr[NNODES + 1];
__device__ int    g_fill[NNODES];
__device__ int    g_incl[NNODES];
__device__ int    g_bsum[256];
__device__ int    g_csr_src[ETOT];
__device__ int    g_esrc[ETOT];
__device__ int    g_edst[ETOT];
__device__ int    g_lu[NLBL];
__device__ int    g_lv[NLBL];
__device__ __half g_xh[(size_t)NNODES * FIN];   // x in fp16
__device__ __half g_hbuf[(size_t)NNODES * DD];  // GEMM output (fp16) / agg input
__device__ __half g_zh[(size_t)NNODES * DD];    // agg output (fp16) / GEMM input
__device__ float  g_als[NNODES * HH];
__device__ float  g_ald[NNODES * HH];
__device__ __half g_prh[(size_t)NNODES * 128];  // scorer P|R per node (fp16)
__device__ __half g_Wt1h[256 * 128];            // W1^T  fp16
__device__ __half g_Wt2h[256 * 256];            // W2^T  fp16
__device__ __half g_Wtsh[128 * 256];            // [Ws1_top|Ws1_bot]^T fp16

// ============================ helpers =======================================
__device__ __forceinline__ uint32_t pack_h2(float a, float b) {
    __half2 h = __floats2half2_rn(a, b);
    return *(uint32_t*)&h;
}

__device__ __forceinline__ void mma16816(float& c0, float& c1, float& c2, float& c3,
                                         uint32_t a0, uint32_t a1, uint32_t a2, uint32_t a3,
                                         uint32_t b0, uint32_t b1) {
    asm volatile(
        "mma.sync.aligned.m16n8k16.row.col.f32.f16.f16.f32 "
        "{%0,%1,%2,%3}, {%4,%5,%6,%7}, {%8,%9}, {%0,%1,%2,%3};"
        : "+f"(c0), "+f"(c1), "+f"(c2), "+f"(c3)
        : "r"(a0), "r"(a1), "r"(a2), "r"(a3), "r"(b0), "r"(b1));
}

__device__ __forceinline__ void ldsm_x4(uint32_t& r0, uint32_t& r1,
                                        uint32_t& r2, uint32_t& r3, uint32_t addr) {
    asm volatile("ldmatrix.sync.aligned.m8n8.x4.shared.b16 {%0,%1,%2,%3}, [%4];"
                 : "=r"(r0), "=r"(r1), "=r"(r2), "=r"(r3) : "r"(addr));
}

__device__ __forceinline__ void ldsm_x2(uint32_t& r0, uint32_t& r1, uint32_t addr) {
    asm volatile("ldmatrix.sync.aligned.m8n8.x2.shared.b16 {%0,%1}, [%2];"
                 : "=r"(r0), "=r"(r1) : "r"(addr));
}

__device__ __forceinline__ int check_is_i64(const long long* q) {
    int ok = 1;
#pragma unroll
    for (int i = 0; i < 8; i++) {
        long long v = q[i];
        if (v < 0 || v >= NNODES) ok = 0;
    }
    return ok;
}

// ---------------- init: zero hist + label conversion + dtype flag -----------
__global__ void init_k(const void* ei, const void* eli) {
    int i = blockIdx.x * blockDim.x + threadIdx.x;
    if (i < NNODES) g_fill[i] = 0;
    if (i < NLBL) {
        if (check_is_i64((const long long*)eli)) {
            const long long* q = (const long long*)eli;
            g_lu[i] = (int)q[i]; g_lv[i] = (int)q[NLBL + i];
        } else {
            const int* q = (const int*)eli;
            g_lu[i] = q[i]; g_lv[i] = q[NLBL + i];
        }
    }
    if (i == 0) g_flag64_e = check_is_i64((const long long*)ei);
}

// ---------------- edge conversion + self loops + histogram ------------------
__global__ void build_edges(const void* ei) {
    int i = blockIdx.x * blockDim.x + threadIdx.x;
    if (i >= ETOT) return;
    int s, d;
    if (i < NEDGES) {
        if (g_flag64_e) {
            const long long* q = (const long long*)ei;
            s = (int)q[i]; d = (int)q[NEDGES + i];
        } else {
            const int* q = (const int*)ei;
            s = q[i]; d = q[NEDGES + i];
        }
    } else {
        s = i - NEDGES; d = s;   // self loop
    }
    g_esrc[i] = s; g_edst[i] = d;
    atomicAdd(&g_fill[d], 1);
}

// ---------------- CSR build: hierarchical scan -------------------------------
__global__ void scan1_k() {
    __shared__ int sh[256];
    int t = threadIdx.x;
    int i = blockIdx.x * 256 + t;
    int v = (i < NNODES) ? g_fill[i] : 0;
    sh[t] = v; __syncthreads();
    for (int o = 1; o < 256; o <<= 1) {
        int a = (t >= o) ? sh[t - o] : 0;
        __syncthreads();
        sh[t] += a;
        __syncthreads();
    }
    if (i < NNODES) g_incl[i] = sh[t];
    if (t == 255) g_bsum[blockIdx.x] = sh[255];
}

__global__ void scan2_k(int nb) {
    __shared__ int sh[256];
    int t = threadIdx.x;
    int v = (t < nb) ? g_bsum[t] : 0;
    sh[t] = v; __syncthreads();
    for (int o = 1; o < 256; o <<= 1) {
        int a = (t >= o) ? sh[t - o] : 0;
        __syncthreads();
        sh[t] += a;
        __syncthreads();
    }
    if (t < nb) g_bsum[t] = sh[t] - v;   // exclusive
}

__global__ void scan3_k() {
    int i = blockIdx.x * blockDim.x + threadIdx.x;
    if (i >= NNODES) return;
    int tot = g_bsum[i >> 8] + g_incl[i];
    int orig = g_fill[i];
    g_rowptr[i + 1] = tot;
    g_fill[i] = tot - orig;              // exclusive offsets for scatter
    if (i == 0) g_rowptr[0] = 0;
}

__global__ void scatter_k() {
    int i = blockIdx.x * blockDim.x + threadIdx.x;
    if (i >= ETOT) return;
    int pos = atomicAdd(&g_fill[g_edst[i]], 1);
    g_csr_src[pos] = g_esrc[i];
}

// ---------------- prep: weight transposes (->fp16) + x conversion -----------
__device__ __forceinline__ void tile_transpose(const float* __restrict__ src,
                                               __half* __restrict__ dst,
                                               int R, int C, int tileIdx,
                                               float (*sh)[33]) {
    int tilesC = C >> 5;
    int tc = tileIdx % tilesC, tr = tileIdx / tilesC;
    int lx = threadIdx.x & 31, ly = threadIdx.x >> 5;   // ly: 0..7
#pragma unroll
    for (int j = 0; j < 32; j += 8)
        sh[ly + j][lx] = src[(size_t)(tr * 32 + ly + j) * C + tc * 32 + lx];
    __syncthreads();
#pragma unroll
    for (int j = 0; j < 32; j += 8)
        dst[(size_t)(tc * 32 + ly + j) * R + tr * 32 + lx] =
            __float2half_rn(sh[lx][ly + j]);
}

#define XCONV_BLOCKS 3125   // NNODES*FIN/8/256

__global__ void prep_k(const float* __restrict__ W1, const float* __restrict__ W2,
                       const float* __restrict__ Ws1, const float* __restrict__ x) {
    __shared__ float sh[32][33];
    int b = blockIdx.x;
    if (b < 32) {
        tile_transpose(W1, g_Wt1h, 128, 256, b, sh);         // -> [256][128]
    } else if (b < 96) {
        tile_transpose(W2, g_Wt2h, 256, 256, b - 32, sh);    // -> [256][256]
    } else if (b < 112) {
        tile_transpose(Ws1, g_Wtsh, 256, 64, b - 96, sh);    // top -> rows [0,64)
    } else if (b < 128) {
        tile_transpose(Ws1 + 256 * 64, g_Wtsh + 64 * 256, 256, 64, b - 112, sh);
    } else {
        int i = (b - 128) * 256 + threadIdx.x;
        if (i < NNODES * FIN / 8) {
            const float4* xp = (const float4*)x;
            float4 a = xp[i * 2], c = xp[i * 2 + 1];
            uint4 u = { pack_h2(a.x, a.y), pack_h2(a.z, a.w),
                        pack_h2(c.x, c.y), pack_h2(c.z, c.w) };
            ((uint4*)g_xh)[i] = u;
        }
    }
}

// ---------------- fp16 mma.sync GEMM (m16n8k16), fp16 gmem + ldmatrix -------
// C[M,NTR] = A[M,KDIM] @ Bt[NTR,KDIM]^T   (half gmem, fp32 accum)
// Block tile 128x64, 8 warps (4 in M x 2 in N), warp tile 32x32.
// LOGITS: fused head logits (64-col block == one head). OUTH: write half2 C.
template <int KDIM, int NTR, bool LOGITS, bool OUTH>
__global__ void __launch_bounds__(256) gemm_mma(
    const __half* __restrict__ A, const __half* __restrict__ Bt,
    void* __restrict__ Cv, int M,
    const float* __restrict__ a_src, const float* __restrict__ a_dst,
    float* __restrict__ als, float* __restrict__ ald)
{
    // smem in half2 units; pitch 20 (80B rows) -> ldmatrix conflict-free
    __shared__ uint32_t As[128 * 20];
    __shared__ uint32_t Bs[64 * 20];
    __shared__ float red[4][128];

    int tid = threadIdx.x;
    int wid = tid >> 5, lane = tid & 31;
    int warp_m = wid & 3, warp_n = wid >> 2;
    int g = lane >> 2, t = lane & 3;

    int rowBase = blockIdx.y * 128;
    int colBase = blockIdx.x * 64;

    uint32_t shA = (uint32_t)__cvta_generic_to_shared(As);
    uint32_t shB = (uint32_t)__cvta_generic_to_shared(Bs);
    uint32_t aAddr = shA + (uint32_t)((warp_m * 32 + (lane & 15)) * 80 + ((lane >> 4) & 1) * 16);
    uint32_t bAddr = shB + (uint32_t)((warp_n * 32 + (lane & 7)) * 80 + ((lane >> 3) & 1) * 16);

    float c[2][4][4];
#pragma unroll
    for (int i = 0; i < 2; i++)
#pragma unroll
        for (int j = 0; j < 4; j++)
#pragma unroll
            for (int k = 0; k < 4; k++) c[i][j][k] = 0.f;

    constexpr int NC = KDIM / 32;
    const uint2 zero2 = {0u, 0u};
    uint2 ra[4], rb[2];
    {
#pragma unroll
        for (int j = 0; j < 4; j++) {
            int idx = tid + 256 * j;
            int r = idx >> 3, q = idx & 7;
            int gr = rowBase + r;
            ra[j] = (gr < M) ? *(const uint2*)(A + (size_t)gr * KDIM + q * 4) : zero2;
        }
#pragma unroll
        for (int j = 0; j < 2; j++) {
            int idx = tid + 256 * j;
            int r = idx >> 3, q = idx & 7;
            rb[j] = *(const uint2*)(Bt + (size_t)(colBase + r) * KDIM + q * 4);
        }
    }

    for (int kc = 0; kc < NC; kc++) {
#pragma unroll
        for (int j = 0; j < 4; j++) {
            int idx = tid + 256 * j;
            int r = idx >> 3, q = idx & 7;
            *(uint2*)&As[r * 20 + q * 2] = ra[j];
        }
#pragma unroll
        for (int j = 0; j < 2; j++) {
            int idx = tid + 256 * j;
            int r = idx >> 3, q = idx & 7;
            *(uint2*)&Bs[r * 20 + q * 2] = rb[j];
        }
        __syncthreads();

        if (kc + 1 < NC) {
            int k0 = (kc + 1) * 32;
#pragma unroll
            for (int j = 0; j < 4; j++) {
                int idx = tid + 256 * j;
                int r = idx >> 3, q = idx & 7;
                int gr = rowBase + r;
                ra[j] = (gr < M) ? *(const uint2*)(A + (size_t)gr * KDIM + k0 + q * 4)
                                 : zero2;
            }
#pragma unroll
            for (int j = 0; j < 2; j++) {
                int idx = tid + 256 * j;
                int r = idx >> 3, q = idx & 7;
                rb[j] = *(const uint2*)(Bt + (size_t)(colBase + r) * KDIM + k0 + q * 4);
            }
        }

#pragma unroll
        for (int ks = 0; ks < 2; ks++) {
            uint32_t koff = ks * 32;   // bytes
            uint32_t a[2][4];
#pragma unroll
            for (int tm = 0; tm < 2; tm++)
                ldsm_x4(a[tm][0], a[tm][1], a[tm][2], a[tm][3],
                        aAddr + tm * 16 * 80 + koff);
            uint32_t b[4][2];
#pragma unroll
            for (int tn = 0; tn < 4; tn++)
                ldsm_x2(b[tn][0], b[tn][1], bAddr + tn * 8 * 80 + koff);
#pragma unroll
            for (int tm = 0; tm < 2; tm++)
#pragma unroll
                for (int tn = 0; tn < 4; tn++)
                    mma16816(c[tm][tn][0], c[tm][tn][1], c[tm][tn][2], c[tm][tn][3],
                             a[tm][0], a[tm][1], a[tm][2], a[tm][3],
                             b[tn][0], b[tn][1]);
        }
        __syncthreads();
    }

    // epilogue: store C (+ fused logits)
    float ps[2][2], pd[2][2];
    if (LOGITS) {
#pragma unroll
        for (int tm = 0; tm < 2; tm++)
            ps[tm][0] = ps[tm][1] = pd[tm][0] = pd[tm][1] = 0.f;
    }
#pragma unroll
    for (int tm = 0; tm < 2; tm++) {
        int r0 = rowBase + warp_m * 32 + tm * 16 + g;
        int r1 = r0 + 8;
#pragma unroll
        for (int tn = 0; tn < 4; tn++) {
            int col = colBase + warp_n * 32 + tn * 8 + t * 2;
            if (LOGITS) {
                float s0 = a_src[col], s1 = a_src[col + 1];
                float d0 = a_dst[col], d1 = a_dst[col + 1];
                ps[tm][0] += c[tm][tn][0] * s0 + c[tm][tn][1] * s1;
                pd[tm][0] += c[tm][tn][0] * d0 + c[tm][tn][1] * d1;
                ps[tm][1] += c[tm][tn][2] * s0 + c[tm][tn][3] * s1;
                pd[tm][1] += c[tm][tn][2] * d0 + c[tm][tn][3] * d1;
            }
            if (OUTH) {
                __half* C = (__half*)Cv;
                if (r0 < M)
                    *(__half2*)(C + (size_t)r0 * NTR + col) =
                        __floats2half2_rn(c[tm][tn][0], c[tm][tn][1]);
                if (r1 < M)
                    *(__half2*)(C + (size_t)r1 * NTR + col) =
                        __floats2half2_rn(c[tm][tn][2], c[tm][tn][3]);
            } else {
                float* C = (float*)Cv;
                if (r0 < M)
                    *(float2*)(C + (size_t)r0 * NTR + col) = make_float2(c[tm][tn][0], c[tm][tn][1]);
                if (r1 < M)
                    *(float2*)(C + (size_t)r1 * NTR + col) = make_float2(c[tm][tn][2], c[tm][tn][3]);
            }
        }
    }
    if (LOGITS) {
#pragma unroll
        for (int tm = 0; tm < 2; tm++)
#pragma unroll
            for (int rr = 0; rr < 2; rr++) {
#pragma unroll
                for (int o = 1; o < 4; o <<= 1) {
                    ps[tm][rr] += __shfl_xor_sync(0xffffffffu, ps[tm][rr], o);
                    pd[tm][rr] += __shfl_xor_sync(0xffffffffu, pd[tm][rr], o);
                }
            }
        __syncthreads();
        if (t == 0) {
#pragma unroll
            for (int tm = 0; tm < 2; tm++) {
                int rl = warp_m * 32 + tm * 16 + g;
                red[warp_n * 2 + 0][rl]     = ps[tm][0];
                red[warp_n * 2 + 0][rl + 8] = ps[tm][1];
                red[warp_n * 2 + 1][rl]     = pd[tm][0];
                red[warp_n * 2 + 1][rl + 8] = pd[tm][1];
            }
        }
        __syncthreads();
        if (tid < 128) {
            int row = rowBase + tid;
            if (row < M) {
                int h = blockIdx.x;   // 64-col block == one head
                als[row * 4 + h] = red[0][tid] + red[2][tid];
                ald[row * 4 + h] = red[1][tid] + red[3][tid];
            }
        }
    }
}

// ---------------- fused softmax + aggregation + bias + ELU (fp16 out) -------
__global__ void __launch_bounds__(256) aggregate_k(const float* __restrict__ bias) {
    int warp = threadIdx.x >> 5, lane = threadIdx.x & 31;
    int n = blockIdx.x * 8 + warp;
    if (n >= NNODES) return;
    int hh = lane >> 3;                         // 8 channels per lane -> head
    int beg = g_rowptr[n], end = g_rowptr[n + 1];
    const __half* hb = g_hbuf;
    float aldn = g_ald[n * 4 + hh];

    float acc[8] = {};
    float psum = 0.f;
#pragma unroll 2
    for (int k = beg; k < end; k++) {
        int s = g_csr_src[k];
        float e = g_als[s * 4 + hh] + aldn;
        float v = e > 0.f ? e : 0.2f * e;
        float w = __expf(v);
        psum += w;
        uint4 u = *(const uint4*)(hb + (size_t)s * 256 + lane * 8);
        const __half2* ph = (const __half2*)&u;
#pragma unroll
        for (int j = 0; j < 4; j++) {
            float2 f = __half22float2(ph[j]);
            acc[2 * j]     = fmaf(w, f.x, acc[2 * j]);
            acc[2 * j + 1] = fmaf(w, f.y, acc[2 * j + 1]);
        }
    }
    float inv = 1.f / psum;
    float4 b0 = *(const float4*)&bias[lane * 8];
    float4 b1 = *(const float4*)&bias[lane * 8 + 4];
    float o[8];
    o[0] = fmaf(acc[0], inv, b0.x); o[1] = fmaf(acc[1], inv, b0.y);
    o[2] = fmaf(acc[2], inv, b0.z); o[3] = fmaf(acc[3], inv, b0.w);
    o[4] = fmaf(acc[4], inv, b1.x); o[5] = fmaf(acc[5], inv, b1.y);
    o[6] = fmaf(acc[6], inv, b1.z); o[7] = fmaf(acc[7], inv, b1.w);
#pragma unroll
    for (int j = 0; j < 8; j++)
        o[j] = o[j] > 0.f ? o[j] : (__expf(o[j]) - 1.f);
    uint4 uo = { pack_h2(o[0], o[1]), pack_h2(o[2], o[3]),
                 pack_h2(o[4], o[5]), pack_h2(o[6], o[7]) };
    *(uint4*)(g_zh + (size_t)n * 256 + lane * 8) = uo;
}

// ---------------- fused scorer: out = relu(P[u]+R[v]+bs1) . Ws2 + bs2 -------
// pr in fp16; lane owns 2 channels via half2.
__global__ void score_k(const float* __restrict__ bs1, const float* __restrict__ Ws2,
                        const float* __restrict__ bs2, float* __restrict__ out) {
    int e = (blockIdx.x * blockDim.x + threadIdx.x) >> 5;
    int lane = threadIdx.x & 31;
    if (e >= NLBL) return;
    int u = g_lu[e], v = g_lv[e];
    const __half2* pu = (const __half2*)(g_prh + (size_t)u * 128);
    const __half2* rv = (const __half2*)(g_prh + (size_t)v * 128 + 64);
    float2 a = __half22float2(pu[lane]);
    float2 b = __half22float2(rv[lane]);
    float2 bb = *(const float2*)&bs1[lane * 2];
    float2 w = *(const float2*)&Ws2[lane * 2];
    float h0 = fmaxf(a.x + b.x + bb.x, 0.f);
    float h1 = fmaxf(a.y + b.y + bb.y, 0.f);
    float s = h0 * w.x + h1 * w.y;
#pragma unroll
    for (int o = 16; o; o >>= 1) s += __shfl_xor_sync(0xffffffffu, s, o);
    if (!lane) out[e] = s + bs2[0];
}

// ---------------- launcher --------------------------------------------------
extern "C" void kernel_launch(void* const* d_in, const int* in_sizes, int n_in,
                              void* d_out, int out_size) {
    const float* x   = (const float*)d_in[0];
    const void*  ei  = d_in[1];
    const void*  eli = d_in[2];
    const float* W1  = (const float*)d_in[3];
    const float* as1 = (const float*)d_in[4];
    const float* ad1 = (const float*)d_in[5];
    const float* b1  = (const float*)d_in[6];
    const float* W2  = (const float*)d_in[7];
    const float* as2 = (const float*)d_in[8];
    const float* ad2 = (const float*)d_in[9];
    const float* b2  = (const float*)d_in[10];
    const float* Ws1 = (const float*)d_in[11];
    const float* bs1 = (const float*)d_in[12];
    const float* Ws2 = (const float*)d_in[13];
    const float* bs2 = (const float*)d_in[14];
    float* out = (float*)d_out;

    __half *xh, *hptr, *zh, *prh, *wt1h, *wt2h, *wtsh;
    float *alsp, *aldp;
    cudaGetSymbolAddress((void**)&xh, g_xh);
    cudaGetSymbolAddress((void**)&hptr, g_hbuf);
    cudaGetSymbolAddress((void**)&zh, g_zh);
    cudaGetSymbolAddress((void**)&prh, g_prh);
    cudaGetSymbolAddress((void**)&wt1h, g_Wt1h);
    cudaGetSymbolAddress((void**)&wt2h, g_Wt2h);
    cudaGetSymbolAddress((void**)&wtsh, g_Wtsh);
    cudaGetSymbolAddress((void**)&alsp, g_als);
    cudaGetSymbolAddress((void**)&aldp, g_ald);

    // side stream + fork/join events (created once, on the non-capture
    // correctness call; host-side only, no device memory involved)
    static cudaStream_t s2 = nullptr;
    static cudaEvent_t evFork = nullptr, evJoin = nullptr;
    if (!s2) {
        cudaStreamCreateWithFlags(&s2, cudaStreamNonBlocking);
        cudaEventCreateWithFlags(&evFork, cudaEventDisableTiming);
        cudaEventCreateWithFlags(&evJoin, cudaEventDisableTiming);
    }

    const int nb = (NNODES + 255) / 256;      // 196
    const int mrows = (NNODES + 127) / 128;   // 391

    // fork: CSR build chain on s2, concurrent with prep + GEMM1
    cudaEventRecord(evFork, 0);
    cudaStreamWaitEvent(s2, evFork, 0);

    init_k<<<(NLBL + 255) / 256, 256, 0, s2>>>(ei, eli);
    build_edges<<<(ETOT + 255) / 256, 256, 0, s2>>>(ei);
    scan1_k<<<nb, 256, 0, s2>>>();
    scan2_k<<<1, 256, 0, s2>>>(nb);
    scan3_k<<<(NNODES + 255) / 256, 256, 0, s2>>>();
    scatter_k<<<(ETOT + 255) / 256, 256, 0, s2>>>();
    cudaEventRecord(evJoin, s2);

    // main stream: fused weight+x prep, then layer-1 GEMM (independent of CSR)
    prep_k<<<128 + XCONV_BLOCKS, 256>>>(W1, W2, Ws1, x);
    gemm_mma<128, 256, true, true><<<dim3(4, mrows), 256>>>(
        xh, wt1h, hptr, NNODES, as1, ad1, alsp, aldp);

    // join: aggregation needs both CSR and logits
    cudaStreamWaitEvent(0, evJoin, 0);

    // ---- layer 1 edge pipeline (softmax fused into aggregation) ----
    aggregate_k<<<(NNODES + 7) / 8, 256>>>(b1);

    // ---- layer 2 ----
    gemm_mma<256, 256, true, true><<<dim3(4, mrows), 256>>>(zh, wt2h, hptr, NNODES,
                                                            as2, ad2, alsp, aldp);
    aggregate_k<<<(NNODES + 7) / 8, 256>>>(b2);

    // ---- scorer (fp16 output) ----
    gemm_mma<256, 128, false, true><<<dim3(2, mrows), 256>>>(zh, wtsh, prh, NNODES,
                                                             nullptr, nullptr, nullptr, nullptr);
    score_k<<<(NLBL + 7) / 8, 256>>>(bs1, Ws2, bs2, out);
}